// round 1
// baseline (speedup 1.0000x reference)
#include <cuda_runtime.h>
#include <cstddef>

#define DMODEL 1024
#define NHEAD  16
#define DK     64
#define BB     128
#define NN     256
#define MROWS  (BB * NN)   // 32768

typedef unsigned long long ull;

// ---- packed fp32x2 helpers (Blackwell FFMA2) ----
__device__ __forceinline__ ull pk2(float x) {
    ull r; asm("mov.b64 %0, {%1, %1};" : "=l"(r) : "f"(x)); return r;
}
__device__ __forceinline__ void fma2(ull& c, ull a, ull b) {
    asm("fma.rn.f32x2 %0, %1, %2, %0;" : "+l"(c) : "l"(a), "l"(b));
}
__device__ __forceinline__ float2 up2(ull v) {
    float lo, hi; asm("mov.b64 {%0, %1}, %2;" : "=f"(lo), "=f"(hi) : "l"(v));
    float2 r; r.x = lo; r.y = hi; return r;
}
__device__ __forceinline__ float fast_exp2(float x) {
    float y; asm("ex2.approx.f32 %0, %1;" : "=f"(y) : "f"(x)); return y;
}

// ---- scratch (static __device__ globals; no allocation allowed) ----
__device__ float g_q[MROWS * DMODEL];
__device__ float g_k[MROWS * DMODEL];
__device__ float g_v[MROWS * DMODEL];
__device__ float g_att[MROWS * DMODEL];

// ============================================================================
// GEMM: C[M][1024] = A[M][1024] @ W[1024][1024]^T + bias
// 128x128 tile, BK=32, 256 threads, 8x8 microtile, packed f32x2 FMAs.
// Shared tiles stored k-major ([k][m]) via lane-major load mapping:
//   store bank = lane  -> conflict-free transpose stores
//   frag loads contiguous 8 floats on pitch-128 rows -> vector LDS
// ============================================================================
__global__ void __launch_bounds__(256, 2) gemm_bias_kernel(
    const float* __restrict__ A, const float* __restrict__ W,
    const float* __restrict__ bias, float* __restrict__ C)
{
    __shared__ float As[32 * 128];
    __shared__ float Bs[32 * 128];

    const int K    = DMODEL;
    const int bm   = blockIdx.y << 7;
    const int bn   = blockIdx.x << 7;
    const int t    = threadIdx.x;
    const int lane = t & 31;
    const int warp = t >> 5;
    const int lrow = lane + ((warp & 3) << 5);   // 0..127, lane-major
    const int kc0  = (warp >> 2) << 2;           // 0 or 4 (k-chunk base)
    const int tx   = t & 15;
    const int ty   = t >> 4;

    const float* Ap = A + (size_t)(bm + lrow) * K;
    const float* Wp = W + (size_t)(bn + lrow) * K;

    ull acc[8][4];
#pragma unroll
    for (int i = 0; i < 8; i++)
#pragma unroll
        for (int j = 0; j < 4; j++) acc[i][j] = 0ull;

    for (int k0 = 0; k0 < K; k0 += 32) {
#pragma unroll
        for (int i = 0; i < 4; i++) {
            const int kk = (kc0 + i) << 2;   // 0,4,...,28
            const float4 av = *(const float4*)(Ap + k0 + kk);
            const float4 wv = *(const float4*)(Wp + k0 + kk);
            As[(kk + 0) * 128 + lrow] = av.x;
            As[(kk + 1) * 128 + lrow] = av.y;
            As[(kk + 2) * 128 + lrow] = av.z;
            As[(kk + 3) * 128 + lrow] = av.w;
            Bs[(kk + 0) * 128 + lrow] = wv.x;
            Bs[(kk + 1) * 128 + lrow] = wv.y;
            Bs[(kk + 2) * 128 + lrow] = wv.z;
            Bs[(kk + 3) * 128 + lrow] = wv.w;
        }
        __syncthreads();

#pragma unroll 8
        for (int k = 0; k < 32; k++) {
            const float4 a0 = *(const float4*)&As[k * 128 + ty * 8];
            const float4 a1 = *(const float4*)&As[k * 128 + ty * 8 + 4];
            const ulonglong2 b0 = *(const ulonglong2*)&Bs[k * 128 + tx * 8];
            const ulonglong2 b1 = *(const ulonglong2*)&Bs[k * 128 + tx * 8 + 4];
            ull bb[4] = { b0.x, b0.y, b1.x, b1.y };
            ull aa[8] = { pk2(a0.x), pk2(a0.y), pk2(a0.z), pk2(a0.w),
                          pk2(a1.x), pk2(a1.y), pk2(a1.z), pk2(a1.w) };
#pragma unroll
            for (int i = 0; i < 8; i++)
#pragma unroll
                for (int j = 0; j < 4; j++)
                    fma2(acc[i][j], aa[i], bb[j]);
        }
        __syncthreads();
    }

    // epilogue: + bias, store
    float bcol[8];
#pragma unroll
    for (int j = 0; j < 8; j++) bcol[j] = bias[bn + tx * 8 + j];

#pragma unroll
    for (int i = 0; i < 8; i++) {
        const size_t row = (size_t)(bm + ty * 8 + i);
        const float2 p0 = up2(acc[i][0]);
        const float2 p1 = up2(acc[i][1]);
        const float2 p2 = up2(acc[i][2]);
        const float2 p3 = up2(acc[i][3]);
        float4 o0, o1;
        o0.x = p0.x + bcol[0]; o0.y = p0.y + bcol[1];
        o0.z = p1.x + bcol[2]; o0.w = p1.y + bcol[3];
        o1.x = p2.x + bcol[4]; o1.y = p2.y + bcol[5];
        o1.z = p3.x + bcol[6]; o1.w = p3.y + bcol[7];
        *(float4*)&C[row * DMODEL + bn + tx * 8]     = o0;
        *(float4*)&C[row * DMODEL + bn + tx * 8 + 4] = o1;
    }
}

// ============================================================================
// Intersample attention: one block per (h, n). S = Q K^T (128x128, d=64),
// softmax over c, O = P V (128x64). All tiles in dynamic shared memory.
// ============================================================================
__global__ void __launch_bounds__(256, 1) attn_kernel(
    const float* __restrict__ gq, const float* __restrict__ gk,
    const float* __restrict__ gv, float* __restrict__ go)
{
    extern __shared__ float sm[];
    float* sQ   = sm;                         // [64][128]  (d-major)
    float* sK   = sm + 64 * 128;              // [64][128]
    float* sS   = sm + 2 * 64 * 128;          // [128][130]
    float* sV   = sS + 128 * 130;             // [128][66]  (c-major, pitch 66)
    float* sInv = sV + 128 * 66;              // [128] reciprocal row sums

    const int n    = blockIdx.x;
    const int h    = blockIdx.y;
    const int t    = threadIdx.x;
    const int lane = t & 31;
    const int warp = t >> 5;
    const int lrow = lane + ((warp & 3) << 5);   // 0..127 (the b / c index)
    const int ch0  = warp >> 2;                  // 0 or 1
    const int tx   = t & 15;
    const int ty   = t >> 4;

    const int    base = n * DMODEL + h * DK;
    const size_t rstr = (size_t)NN * DMODEL;     // stride between batch rows

    const float* qp = gq + base + (size_t)lrow * rstr;
    const float* kp = gk + base + (size_t)lrow * rstr;
    const float* vp = gv + base + (size_t)lrow * rstr;

    // load Q,K (transposed to [d][b]) and V (natural [c][d], pitch 66)
#pragma unroll
    for (int i = 0; i < 8; i++) {
        const int d = (ch0 + 2 * i) * 4;          // 0..60
        const float4 qv = *(const float4*)(qp + d);
        const float4 kv = *(const float4*)(vp == vp ? qp + d : qp + d), // placeholder avoided below
                     dummy = qv; (void)dummy; (void)kv;
        const float4 qv2 = qv;
        const float4 kvr = *(const float4*)(kp + d);
        const float4 vvr = *(const float4*)(vp + d);
        sQ[(d + 0) * 128 + lrow] = qv2.x;
        sQ[(d + 1) * 128 + lrow] = qv2.y;
        sQ[(d + 2) * 128 + lrow] = qv2.z;
        sQ[(d + 3) * 128 + lrow] = qv2.w;
        sK[(d + 0) * 128 + lrow] = kvr.x;
        sK[(d + 1) * 128 + lrow] = kvr.y;
        sK[(d + 2) * 128 + lrow] = kvr.z;
        sK[(d + 3) * 128 + lrow] = kvr.w;
        sV[lrow * 66 + d + 0] = vvr.x;
        sV[lrow * 66 + d + 1] = vvr.y;
        sV[lrow * 66 + d + 2] = vvr.z;
        sV[lrow * 66 + d + 3] = vvr.w;
    }
    __syncthreads();

    // ---- S = Q K^T (rows b, cols c), 8x8 microtile over d=64 ----
    {
        ull acc[8][4];
#pragma unroll
        for (int i = 0; i < 8; i++)
#pragma unroll
            for (int j = 0; j < 4; j++) acc[i][j] = 0ull;

#pragma unroll 8
        for (int k = 0; k < 64; k++) {
            const float4 a0 = *(const float4*)&sQ[k * 128 + ty * 8];
            const float4 a1 = *(const float4*)&sQ[k * 128 + ty * 8 + 4];
            const ulonglong2 b0 = *(const ulonglong2*)&sK[k * 128 + tx * 8];
            const ulonglong2 b1 = *(const ulonglong2*)&sK[k * 128 + tx * 8 + 4];
            ull bb[4] = { b0.x, b0.y, b1.x, b1.y };
            ull aa[8] = { pk2(a0.x), pk2(a0.y), pk2(a0.z), pk2(a0.w),
                          pk2(a1.x), pk2(a1.y), pk2(a1.z), pk2(a1.w) };
#pragma unroll
            for (int i = 0; i < 8; i++)
#pragma unroll
                for (int j = 0; j < 4; j++)
                    fma2(acc[i][j], aa[i], bb[j]);
        }
#pragma unroll
        for (int i = 0; i < 8; i++) {
            const int row = ty * 8 + i;
#pragma unroll
            for (int j = 0; j < 4; j++)
                *(ull*)&sS[row * 130 + tx * 8 + 2 * j] = acc[i][j];
        }
    }
    __syncthreads();

    // ---- softmax over c (one thread per row) ----
    if (t < 128) {
        float* sr = sS + t * 130;
        float mx = -1e30f;
#pragma unroll 8
        for (int c = 0; c < 128; c++) mx = fmaxf(mx, sr[c]);
        const float cf = 0.125f * 1.4426950408889634f;  // scale * log2(e)
        float sum = 0.f;
#pragma unroll 8
        for (int c = 0; c < 128; c++) {
            const float e = fast_exp2((sr[c] - mx) * cf);
            sr[c] = e;
            sum += e;
        }
        sInv[t] = 1.0f / sum;
    }
    __syncthreads();

    // ---- O = P V (128x64), 8x4 microtile over c=128 ----
    {
        ull oc[8][2];
#pragma unroll
        for (int i = 0; i < 8; i++) { oc[i][0] = 0ull; oc[i][1] = 0ull; }

#pragma unroll 4
        for (int c = 0; c < 128; c++) {
            const ull b0 = *(const ull*)&sV[c * 66 + tx * 4];
            const ull b1 = *(const ull*)&sV[c * 66 + tx * 4 + 2];
#pragma unroll
            for (int i = 0; i < 8; i++) {
                const ull a = pk2(sS[(ty * 8 + i) * 130 + c]);
                fma2(oc[i][0], a, b0);
                fma2(oc[i][1], a, b1);
            }
        }

#pragma unroll
        for (int i = 0; i < 8; i++) {
            const int b   = ty * 8 + i;
            const float inv = sInv[b];
            const float2 p0 = up2(oc[i][0]);
            const float2 p1 = up2(oc[i][1]);
            float4 o;
            o.x = p0.x * inv; o.y = p0.y * inv;
            o.z = p1.x * inv; o.w = p1.y * inv;
            *(float4*)&go[base + (size_t)b * rstr + tx * 4] = o;
        }
    }
}

// ============================================================================
// kernel_launch
// ============================================================================
extern "C" void kernel_launch(void* const* d_in, const int* in_sizes, int n_in,
                              void* d_out, int out_size)
{
    const float* query = (const float*)d_in[0];
    const float* key   = (const float*)d_in[1];
    const float* value = (const float*)d_in[2];
    const float* Wq    = (const float*)d_in[3];
    const float* bq    = (const float*)d_in[4];
    const float* Wk    = (const float*)d_in[5];
    const float* bk    = (const float*)d_in[6];
    const float* Wv    = (const float*)d_in[7];
    const float* bv    = (const float*)d_in[8];
    const float* Wo    = (const float*)d_in[9];
    const float* bo    = (const float*)d_in[10];
    float* out = (float*)d_out;

    float *pq, *pk, *pv, *pa;
    cudaGetSymbolAddress((void**)&pq, g_q);
    cudaGetSymbolAddress((void**)&pk, g_k);
    cudaGetSymbolAddress((void**)&pv, g_v);
    cudaGetSymbolAddress((void**)&pa, g_att);

    const dim3 ggrid(DMODEL / 128, MROWS / 128);   // (8, 256)
    gemm_bias_kernel<<<ggrid, 256>>>(query, Wq, bq, pq);
    gemm_bias_kernel<<<ggrid, 256>>>(key,   Wk, bk, pk);
    gemm_bias_kernel<<<ggrid, 256>>>(value, Wv, bv, pv);

    const int smem = (64 * 128 * 2 + 128 * 130 + 128 * 66 + 128) * 4;  // 166400 B
    cudaFuncSetAttribute(attn_kernel, cudaFuncAttributeMaxDynamicSharedMemorySize, smem);
    attn_kernel<<<dim3(NN, NHEAD), 256, smem>>>(pq, pk, pv, pa);

    gemm_bias_kernel<<<ggrid, 256>>>(pa, Wo, bo, out);
}

// round 3
// speedup vs baseline: 4.5080x; 4.5080x over previous
#include <cuda_runtime.h>
#include <cuda_bf16.h>
#include <cstdint>
#include <cstddef>

#define DMODEL 1024
#define NHEAD  16
#define DK     64
#define BB     128
#define NN     256
#define MROWS  (BB * NN)   // 32768

typedef unsigned long long ull;

// ============================ helpers ============================
__device__ __forceinline__ uint32_t pack2(float x, float y) {  // low=x, high=y
    uint32_t r; asm("cvt.rn.bf16x2.f32 %0, %2, %1;" : "=r"(r) : "f"(x), "f"(y)); return r;
}
__device__ __forceinline__ float fast_exp2(float x) {
    float y; asm("ex2.approx.f32 %0, %1;" : "=f"(y) : "f"(x)); return y;
}
__device__ __forceinline__ ull pk2(float x) {
    ull r; asm("mov.b64 %0, {%1, %1};" : "=l"(r) : "f"(x)); return r;
}
__device__ __forceinline__ void fma2(ull& c, ull a, ull b) {
    asm("fma.rn.f32x2 %0, %1, %2, %0;" : "+l"(c) : "l"(a), "l"(b));
}
__device__ __forceinline__ float2 up2(ull v) {
    float lo, hi; asm("mov.b64 {%0, %1}, %2;" : "=f"(lo), "=f"(hi) : "l"(v));
    float2 r; r.x = lo; r.y = hi; return r;
}
__device__ __forceinline__ void mma16816(float* c, const uint32_t* a, const uint32_t* b) {
    asm volatile("mma.sync.aligned.m16n8k16.row.col.f32.bf16.bf16.f32 "
        "{%0,%1,%2,%3}, {%4,%5,%6,%7}, {%8,%9}, {%0,%1,%2,%3};"
        : "+f"(c[0]), "+f"(c[1]), "+f"(c[2]), "+f"(c[3])
        : "r"(a[0]), "r"(a[1]), "r"(a[2]), "r"(a[3]), "r"(b[0]), "r"(b[1]));
}

// ---- scratch ----
__device__ float g_q[MROWS * DMODEL];
__device__ float g_k[MROWS * DMODEL];
__device__ float g_v[MROWS * DMODEL];
__device__ float g_att[MROWS * DMODEL];

// ============================================================================
// HMMA GEMM: C[M][1024] = A[M][1024] @ W[1024][1024]^T + bias
// BM=128, BN=128, BK=32, 8 warps (warp tile 64x32), bf16 hi/lo 3-term split,
// fp32 accumulators. Smem tiles: pitch 40 bf16 (80B) rows -> conflict-free
// fragment reads. Double-buffered stages, GMEM loads pipelined one stage ahead.
// ============================================================================
#define TP   80          // tile pitch bytes (40 bf16)
#define TSZ  10240       // one tile: 128 rows * 80 B
#define STG_BYTES 40960  // Ah, Al, Wh, Wl
#define NSTAGE 32

__global__ void __launch_bounds__(256, 1) gemm_mma(
    const float* __restrict__ A, const float* __restrict__ W,
    const float* __restrict__ bias, float* __restrict__ C)
{
    extern __shared__ __align__(16) char dsm[];

    const int t    = threadIdx.x;
    const int lane = t & 31;
    const int wid  = t >> 5;
    const int bm   = blockIdx.y << 7;
    const int bn   = blockIdx.x << 7;

    // loader mapping: q = float4 col (0..7), rb = row base (0..31), rows rb+32i
    const int q  = t & 7;
    const int rb = t >> 3;
    const float* Ap = A + (size_t)(bm + rb) * DMODEL + q * 4;
    const float* Wp = W + (size_t)(bn + rb) * DMODEL + q * 4;

    // warp tile: wm in {0,64}, wn in {0,32,64,96}
    const int wm = (wid >> 2) * 64;
    const int wn = (wid & 3) * 32;
    const int g  = lane >> 2;
    const int tg = lane & 3;

    uint32_t baseA[4], baseB[4];
#pragma unroll
    for (int mf = 0; mf < 4; mf++) baseA[mf] = (uint32_t)((wm + mf * 16 + g) * TP + tg * 4);
#pragma unroll
    for (int nf = 0; nf < 4; nf++) baseB[nf] = (uint32_t)((wn + nf * 8 + g) * TP + tg * 4);

    float acc[4][4][4];
#pragma unroll
    for (int i = 0; i < 4; i++)
#pragma unroll
        for (int j = 0; j < 4; j++)
#pragma unroll
            for (int e = 0; e < 4; e++) acc[i][j][e] = 0.f;

    float4 va[4], vw[4];

    // ---- prologue: load + store stage 0 ----
#pragma unroll
    for (int i = 0; i < 4; i++) {
        va[i] = *(const float4*)(Ap + (size_t)(32 * i) * DMODEL);
        vw[i] = *(const float4*)(Wp + (size_t)(32 * i) * DMODEL);
    }
    {
        char* stg = dsm;
#pragma unroll
        for (int i = 0; i < 4; i++) {
            const uint32_t off = (uint32_t)((rb + 32 * i) * TP + q * 8);
            uint32_t h01 = pack2(va[i].x, va[i].y), h23 = pack2(va[i].z, va[i].w);
            float f0 = __uint_as_float(h01 << 16), f1 = __uint_as_float(h01 & 0xffff0000u);
            float f2 = __uint_as_float(h23 << 16), f3 = __uint_as_float(h23 & 0xffff0000u);
            *(uint2*)(stg + off)       = make_uint2(h01, h23);
            *(uint2*)(stg + TSZ + off) = make_uint2(pack2(va[i].x - f0, va[i].y - f1),
                                                    pack2(va[i].z - f2, va[i].w - f3));
            h01 = pack2(vw[i].x, vw[i].y); h23 = pack2(vw[i].z, vw[i].w);
            f0 = __uint_as_float(h01 << 16); f1 = __uint_as_float(h01 & 0xffff0000u);
            f2 = __uint_as_float(h23 << 16); f3 = __uint_as_float(h23 & 0xffff0000u);
            *(uint2*)(stg + 2 * TSZ + off) = make_uint2(h01, h23);
            *(uint2*)(stg + 3 * TSZ + off) = make_uint2(pack2(vw[i].x - f0, vw[i].y - f1),
                                                        pack2(vw[i].z - f2, vw[i].w - f3));
        }
    }
    __syncthreads();

    for (int s = 0; s < NSTAGE; s++) {
        // prefetch next stage into registers
        if (s + 1 < NSTAGE) {
            const int col = (s + 1) * 32;
#pragma unroll
            for (int i = 0; i < 4; i++) {
                va[i] = *(const float4*)(Ap + (size_t)(32 * i) * DMODEL + col);
                vw[i] = *(const float4*)(Wp + (size_t)(32 * i) * DMODEL + col);
            }
        }

        // ---- compute on buffer s&1 ----
        const char* stg = dsm + (s & 1) * STG_BYTES;
#pragma unroll
        for (int ks = 0; ks < 2; ks++) {
#pragma unroll
            for (int term = 0; term < 3; term++) {
                const char* ab = stg + (term == 1 ? TSZ : 0) + ks * 32;
                const char* bb = stg + 2 * TSZ + (term == 2 ? TSZ : 0) + ks * 32;
                uint32_t breg[4][2];
#pragma unroll
                for (int nf = 0; nf < 4; nf++) {
                    breg[nf][0] = *(const uint32_t*)(bb + baseB[nf]);
                    breg[nf][1] = *(const uint32_t*)(bb + baseB[nf] + 16);
                }
#pragma unroll
                for (int mf = 0; mf < 4; mf++) {
                    uint32_t areg[4];
                    areg[0] = *(const uint32_t*)(ab + baseA[mf]);
                    areg[1] = *(const uint32_t*)(ab + baseA[mf] + 8 * TP);
                    areg[2] = *(const uint32_t*)(ab + baseA[mf] + 16);
                    areg[3] = *(const uint32_t*)(ab + baseA[mf] + 8 * TP + 16);
#pragma unroll
                    for (int nf = 0; nf < 4; nf++)
                        mma16816(acc[mf][nf], areg, breg[nf]);
                }
            }
        }

        // ---- store next stage into buffer (s+1)&1 ----
        if (s + 1 < NSTAGE) {
            char* nstg = dsm + ((s + 1) & 1) * STG_BYTES;
#pragma unroll
            for (int i = 0; i < 4; i++) {
                const uint32_t off = (uint32_t)((rb + 32 * i) * TP + q * 8);
                uint32_t h01 = pack2(va[i].x, va[i].y), h23 = pack2(va[i].z, va[i].w);
                float f0 = __uint_as_float(h01 << 16), f1 = __uint_as_float(h01 & 0xffff0000u);
                float f2 = __uint_as_float(h23 << 16), f3 = __uint_as_float(h23 & 0xffff0000u);
                *(uint2*)(nstg + off)       = make_uint2(h01, h23);
                *(uint2*)(nstg + TSZ + off) = make_uint2(pack2(va[i].x - f0, va[i].y - f1),
                                                         pack2(va[i].z - f2, va[i].w - f3));
                h01 = pack2(vw[i].x, vw[i].y); h23 = pack2(vw[i].z, vw[i].w);
                f0 = __uint_as_float(h01 << 16); f1 = __uint_as_float(h01 & 0xffff0000u);
                f2 = __uint_as_float(h23 << 16); f3 = __uint_as_float(h23 & 0xffff0000u);
                *(uint2*)(nstg + 2 * TSZ + off) = make_uint2(h01, h23);
                *(uint2*)(nstg + 3 * TSZ + off) = make_uint2(pack2(vw[i].x - f0, vw[i].y - f1),
                                                             pack2(vw[i].z - f2, vw[i].w - f3));
            }
        }
        __syncthreads();
    }

    // ---- epilogue: acc + bias -> C ----
#pragma unroll
    for (int mf = 0; mf < 4; mf++) {
        const int row0 = bm + wm + mf * 16 + (lane >> 2);
#pragma unroll
        for (int nf = 0; nf < 4; nf++) {
            const int col = bn + wn + nf * 8 + (lane & 3) * 2;
            const float bx = bias[col], by = bias[col + 1];
            float2 o0, o1;
            o0.x = acc[mf][nf][0] + bx; o0.y = acc[mf][nf][1] + by;
            o1.x = acc[mf][nf][2] + bx; o1.y = acc[mf][nf][3] + by;
            *(float2*)&C[(size_t)row0 * DMODEL + col]       = o0;
            *(float2*)&C[(size_t)(row0 + 8) * DMODEL + col] = o1;
        }
    }
}

// ============================================================================
// Intersample attention: one block per (h, n). S = Q K^T (128x128, d=64),
// softmax over c, O = P V (128x64). FFMA2 path (known good, 813us).
// ============================================================================
__global__ void __launch_bounds__(256, 1) attn_kernel(
    const float* __restrict__ gq, const float* __restrict__ gk,
    const float* __restrict__ gv, float* __restrict__ go)
{
    extern __shared__ float sm[];
    float* sQ   = sm;                         // [64][128]
    float* sK   = sm + 64 * 128;              // [64][128]
    float* sS   = sm + 2 * 64 * 128;          // [128][130]
    float* sV   = sS + 128 * 130;             // [128][66]
    float* sInv = sV + 128 * 66;              // [128]

    const int n    = blockIdx.x;
    const int h    = blockIdx.y;
    const int t    = threadIdx.x;
    const int lane = t & 31;
    const int warp = t >> 5;
    const int lrow = lane + ((warp & 3) << 5);
    const int ch0  = warp >> 2;
    const int tx   = t & 15;
    const int ty   = t >> 4;

    const int    base = n * DMODEL + h * DK;
    const size_t rstr = (size_t)NN * DMODEL;

    const float* qp = gq + base + (size_t)lrow * rstr;
    const float* kp = gk + base + (size_t)lrow * rstr;
    const float* vp = gv + base + (size_t)lrow * rstr;

#pragma unroll
    for (int i = 0; i < 8; i++) {
        const int d = (ch0 + 2 * i) * 4;
        const float4 qvr = *(const float4*)(qp + d);
        const float4 kvr = *(const float4*)(kp + d);
        const float4 vvr = *(const float4*)(vp + d);
        sQ[(d + 0) * 128 + lrow] = qvr.x;
        sQ[(d + 1) * 128 + lrow] = qvr.y;
        sQ[(d + 2) * 128 + lrow] = qvr.z;
        sQ[(d + 3) * 128 + lrow] = qvr.w;
        sK[(d + 0) * 128 + lrow] = kvr.x;
        sK[(d + 1) * 128 + lrow] = kvr.y;
        sK[(d + 2) * 128 + lrow] = kvr.z;
        sK[(d + 3) * 128 + lrow] = kvr.w;
        sV[lrow * 66 + d + 0] = vvr.x;
        sV[lrow * 66 + d + 1] = vvr.y;
        sV[lrow * 66 + d + 2] = vvr.z;
        sV[lrow * 66 + d + 3] = vvr.w;
    }
    __syncthreads();

    {
        ull acc[8][4];
#pragma unroll
        for (int i = 0; i < 8; i++)
#pragma unroll
            for (int j = 0; j < 4; j++) acc[i][j] = 0ull;

#pragma unroll 8
        for (int k = 0; k < 64; k++) {
            const float4 a0 = *(const float4*)&sQ[k * 128 + ty * 8];
            const float4 a1 = *(const float4*)&sQ[k * 128 + ty * 8 + 4];
            const ulonglong2 b0 = *(const ulonglong2*)&sK[k * 128 + tx * 8];
            const ulonglong2 b1 = *(const ulonglong2*)&sK[k * 128 + tx * 8 + 4];
            ull bb[4] = { b0.x, b0.y, b1.x, b1.y };
            ull aa[8] = { pk2(a0.x), pk2(a0.y), pk2(a0.z), pk2(a0.w),
                          pk2(a1.x), pk2(a1.y), pk2(a1.z), pk2(a1.w) };
#pragma unroll
            for (int i = 0; i < 8; i++)
#pragma unroll
                for (int j = 0; j < 4; j++)
                    fma2(acc[i][j], aa[i], bb[j]);
        }
#pragma unroll
        for (int i = 0; i < 8; i++) {
            const int row = ty * 8 + i;
#pragma unroll
            for (int j = 0; j < 4; j++)
                *(ull*)&sS[row * 130 + tx * 8 + 2 * j] = acc[i][j];
        }
    }
    __syncthreads();

    if (t < 128) {
        float* sr = sS + t * 130;
        float mx = -1e30f;
#pragma unroll 8
        for (int c = 0; c < 128; c++) mx = fmaxf(mx, sr[c]);
        const float cf = 0.125f * 1.4426950408889634f;
        float sum = 0.f;
#pragma unroll 8
        for (int c = 0; c < 128; c++) {
            const float e = fast_exp2((sr[c] - mx) * cf);
            sr[c] = e;
            sum += e;
        }
        sInv[t] = 1.0f / sum;
    }
    __syncthreads();

    {
        ull oc[8][2];
#pragma unroll
        for (int i = 0; i < 8; i++) { oc[i][0] = 0ull; oc[i][1] = 0ull; }

#pragma unroll 4
        for (int c = 0; c < 128; c++) {
            const ull b0 = *(const ull*)&sV[c * 66 + tx * 4];
            const ull b1 = *(const ull*)&sV[c * 66 + tx * 4 + 2];
#pragma unroll
            for (int i = 0; i < 8; i++) {
                const ull a = pk2(sS[(ty * 8 + i) * 130 + c]);
                fma2(oc[i][0], a, b0);
                fma2(oc[i][1], a, b1);
            }
        }

#pragma unroll
        for (int i = 0; i < 8; i++) {
            const int b   = ty * 8 + i;
            const float inv = sInv[b];
            const float2 p0 = up2(oc[i][0]);
            const float2 p1 = up2(oc[i][1]);
            float4 o;
            o.x = p0.x * inv; o.y = p0.y * inv;
            o.z = p1.x * inv; o.w = p1.y * inv;
            *(float4*)&go[base + (size_t)b * rstr + tx * 4] = o;
        }
    }
}

// ============================================================================
// kernel_launch
// ============================================================================
extern "C" void kernel_launch(void* const* d_in, const int* in_sizes, int n_in,
                              void* d_out, int out_size)
{
    const float* query = (const float*)d_in[0];
    const float* key   = (const float*)d_in[1];
    const float* value = (const float*)d_in[2];
    const float* Wq    = (const float*)d_in[3];
    const float* bq    = (const float*)d_in[4];
    const float* Wk    = (const float*)d_in[5];
    const float* bk    = (const float*)d_in[6];
    const float* Wv    = (const float*)d_in[7];
    const float* bv    = (const float*)d_in[8];
    const float* Wo    = (const float*)d_in[9];
    const float* bo    = (const float*)d_in[10];
    float* out = (float*)d_out;

    float *pq, *pk, *pv, *pa;
    cudaGetSymbolAddress((void**)&pq, g_q);
    cudaGetSymbolAddress((void**)&pk, g_k);
    cudaGetSymbolAddress((void**)&pv, g_v);
    cudaGetSymbolAddress((void**)&pa, g_att);

    const int gsmem = 2 * STG_BYTES;   // 81920 B
    const int asmem = (64 * 128 * 2 + 128 * 130 + 128 * 66 + 128) * 4;
    static int s_attr = 0;
    if (!s_attr) {
        cudaFuncSetAttribute(gemm_mma, cudaFuncAttributeMaxDynamicSharedMemorySize, gsmem);
        cudaFuncSetAttribute(attn_kernel, cudaFuncAttributeMaxDynamicSharedMemorySize, asmem);
        s_attr = 1;
    }

    const dim3 ggrid(DMODEL / 128, MROWS / 128);   // (8, 256)
    gemm_mma<<<ggrid, 256, gsmem>>>(query, Wq, bq, pq);
    gemm_mma<<<ggrid, 256, gsmem>>>(key,   Wk, bk, pk);
    gemm_mma<<<ggrid, 256, gsmem>>>(value, Wv, bv, pv);

    attn_kernel<<<dim3(NN, NHEAD), 256, asmem>>>(pq, pk, pv, pa);

    gemm_mma<<<ggrid, 256, gsmem>>>(pa, Wo, bo, out);
}